// round 2
// baseline (speedup 1.0000x reference)
#include <cuda_runtime.h>
#include <math.h>

// Problem constants (fixed shapes for this problem instance)
#define Ns     512
#define DEG    8
#define Fdim   128
#define Hd     256
#define Md     256
#define Od     64
#define Pd     2
#define Sd     64      // num_starts
#define HISTN  10
#define STEPS  5120    // 10*N, all steps active
#define NMSG   632     // steps whose message is consumed by children: 64+8*i < 5120
#define GRIDB  148

// ---------------- device globals (scratch; no allocation allowed) ------------
__device__ int   d_q[STEPS];
__device__ int   d_occ[STEPS];
__device__ int   d_prevs[STEPS];
__device__ int   d_lvl[STEPS];
__device__ int   d_order[STEPS];
__device__ int   d_loff[STEPS + 2];
__device__ int   d_cur[STEPS + 2];
__device__ int   d_nlev;
__device__ int   d_fslot[Ns];
__device__ float d_states[Ns * HISTN * Hd];   // 5.24 MB ring buffers
__device__ float d_msg[NMSG * Md];            // per-step produced messages
__device__ float d_AmW[Md * Hd];              // [m][x] = (1/16) * dot(Wk[x,:], Wq[m,:])
__device__ float d_u[Hd];                     // (1/16) * Wk @ bq
__device__ float d_Wrs[Hd * Hd];              // sum of the 4 row-blocks of Wr
__device__ float d_WkT[Hd * Hd];              // Wk transposed
__device__ unsigned d_bcnt = 0;               // grid barrier count
__device__ unsigned d_bgen = 0;               // grid barrier generation

// ---------------- prep kernels ----------------------------------------------

// WkT[h][x] = Wk[x][h]
__global__ void k_transpose(const float* __restrict__ Wk) {
    __shared__ float tile[32][33];
    int x0 = blockIdx.x * 32, y0 = blockIdx.y * 32;
    for (int i = threadIdx.y; i < 32; i += 8)
        tile[i][threadIdx.x] = Wk[(y0 + i) * Hd + x0 + threadIdx.x];
    __syncthreads();
    for (int i = threadIdx.y; i < 32; i += 8)
        d_WkT[(x0 + i) * Hd + y0 + threadIdx.x] = tile[threadIdx.x][i];
}

// AmW[m][x] = (1/16) sum_h Wq[m][h] * WkT[h][x]
__global__ void k_amw(const float* __restrict__ Wq) {
    __shared__ float wq[Hd];
    int m = blockIdx.x, x = threadIdx.x;
    wq[x] = Wq[m * Hd + x];
    __syncthreads();
    float acc = 0.f;
#pragma unroll 4
    for (int h = 0; h < Hd; h++) acc += wq[h] * d_WkT[h * Hd + x];
    d_AmW[m * Hd + x] = acc * 0.0625f;
}

// u[x] = (1/16) sum_h WkT[h][x] * bq[h]
__global__ void k_u(const float* __restrict__ bq) {
    int x = threadIdx.x;
    float acc = 0.f;
#pragma unroll 4
    for (int h = 0; h < Hd; h++) acc += d_WkT[h * Hd + x] * bq[h];
    d_u[x] = acc * 0.0625f;
}

// Wrs[x][h] = Wr[x][h] + Wr[256+x][h] + Wr[512+x][h] + Wr[768+x][h]
__global__ void k_wrs(const float* __restrict__ Wr) {
    int x = blockIdx.x, h = threadIdx.x;
    float s = Wr[x * Hd + h] + Wr[(Hd + x) * Hd + h]
            + Wr[(2 * Hd + x) * Hd + h] + Wr[(3 * Hd + x) * Hd + h];
    d_Wrs[x * Hd + h] = s;
}

// encoded = xa @ We + be -> states slot 0
__global__ void k_init_states(const float* __restrict__ xa,
                              const float* __restrict__ We,
                              const float* __restrict__ be) {
    __shared__ float xs[Fdim];
    int n = blockIdx.x, h = threadIdx.x;
    if (h < Fdim) xs[h] = xa[n * Fdim + h];
    __syncthreads();
    float acc = be[h];
#pragma unroll 4
    for (int f = 0; f < Fdim; f++) acc += xs[f] * We[f * Hd + h];
    d_states[(n * HISTN + 0) * Hd + h] = acc;
}

// ---------------- schedule builder (single block) ----------------------------
__global__ void k_build(const int* __restrict__ neighbors) {
    __shared__ int q_s[STEPS];       // 20 KB
    __shared__ int nb_s[Ns * DEG];   // 16 KB
    __shared__ int changed, maxl;
    const int tid = threadIdx.x;     // 1024 threads

    for (int x = tid; x < Ns * DEG; x += 1024) nb_s[x] = neighbors[x];
    if (tid < Sd) q_s[tid] = tid;
    __syncthreads();

    // node sequence: q[i] = nbrs[q[(i-64)/8]][(i-64)%8], 3 rounds suffice
    int v = Sd;
    while (v < STEPS) {
        int nv = min(STEPS, Sd + DEG * v);
        for (int x = v + tid; x < nv; x += 1024)
            q_s[x] = nb_s[q_s[(x - Sd) >> 3] * DEG + ((x - Sd) & 7)];
        __syncthreads();
        v = nv;
    }
    for (int x = tid; x < STEPS; x += 1024) d_q[x] = q_s[x];

    // per-node occurrence scan (thread = node); smem broadcast reads
    if (tid < Ns) {
        int cnt = 0, last = -1;
        for (int ii = 0; ii < STEPS; ii++) {
            if (q_s[ii] == tid) {
                d_occ[ii] = cnt; d_prevs[ii] = last;
                last = ii; cnt++;
            }
        }
        d_fslot[tid] = cnt % HISTN;  // (count-1) % HIST with count = 1+cnt
    }
    __syncthreads();

    // levels by monotone relaxation: lvl[i] = 1 + max(lvl[parent], lvl[prev_same])
    for (int x = tid; x < STEPS; x += 1024) d_lvl[x] = 0;
    __syncthreads();
    while (true) {
        if (tid == 0) changed = 0;
        __syncthreads();
        for (int x = tid; x < STEPS; x += 1024) {
            int nl = 0;
            if (x >= Sd) nl = d_lvl[(x - Sd) >> 3] + 1;
            int pv = d_prevs[x];
            if (pv >= 0) { int t = d_lvl[pv] + 1; if (t > nl) nl = t; }
            if (nl > d_lvl[x]) { d_lvl[x] = nl; changed = 1; }
        }
        __syncthreads();
        if (!changed) break;
        __syncthreads();
    }

    // nlevels
    if (tid == 0) maxl = 0;
    __syncthreads();
    { int lm = 0;
      for (int x = tid; x < STEPS; x += 1024) lm = max(lm, d_lvl[x]);
      atomicMax(&maxl, lm); }
    __syncthreads();
    int nlev = maxl + 1;
    if (tid == 0) d_nlev = nlev;

    // counting sort by level
    for (int x = tid; x < STEPS + 2; x += 1024) d_loff[x] = 0;
    __syncthreads();
    for (int x = tid; x < STEPS; x += 1024) atomicAdd(&d_loff[d_lvl[x] + 1], 1);
    __syncthreads();
    if (tid == 0) for (int L = 1; L <= nlev; L++) d_loff[L] += d_loff[L - 1];
    __syncthreads();
    for (int x = tid; x < STEPS + 2; x += 1024) d_cur[x] = d_loff[x];
    __syncthreads();
    for (int x = tid; x < STEPS; x += 1024) {
        int p = atomicAdd(&d_cur[d_lvl[x]], 1);
        d_order[p] = x;
    }
}

// ---------------- grid barrier -----------------------------------------------
__device__ __forceinline__ unsigned grid_barrier(unsigned gen) {
    __syncthreads();
    if (threadIdx.x == 0) {
        __threadfence();
        if (atomicAdd(&d_bcnt, 1u) == gridDim.x - 1) {
            d_bcnt = 0;
            __threadfence();
            *((volatile unsigned*)&d_bgen) = gen + 1;
        } else {
            while (*((volatile unsigned*)&d_bgen) != gen + 1) __nanosleep(64);
        }
        __threadfence();
    }
    __syncthreads();
    return gen + 1;
}

// ---------------- main persistent level-parallel kernel ----------------------
__global__ __launch_bounds__(256) void k_main(const float* __restrict__ fm,
                                              const float* __restrict__ br,
                                              const float* __restrict__ bm,
                                              const float* __restrict__ Wm) {
    __shared__ float m_s[Md], t_s[Hd], vv_s[Hd], cat_s[Hd + Md];
    __shared__ float red_s[4 * Hd];
    __shared__ float lg_s[HISTN], att_s[HISTN];
    __shared__ int   info_s[3];
    const int tid = threadIdx.x;

    unsigned gen = *((volatile unsigned*)&d_bgen);
    const int nlev = d_nlev;

    for (int L = 0; L < nlev; L++) {
        const int lo = d_loff[L], hi = d_loff[L + 1];
        for (int pos = lo + blockIdx.x; pos < hi; pos += gridDim.x) {
            if (tid == 0) {
                int i = d_order[pos];
                info_s[0] = i; info_s[1] = d_q[i]; info_s[2] = d_occ[i];
            }
            __syncthreads();
            const int i = info_s[0], n = info_s[1], occ = info_s[2];
            const int c = occ + 1;
            const int nval  = (c < HISTN) ? c : HISTN;
            const int wslot = c % HISTN;

            // incoming message
            if (i < Sd) m_s[tid] = __ldg(&fm[i * Md + tid]);
            else        m_s[tid] = __ldcg(&d_msg[((i - Sd) >> 3) * Md + tid]);
            __syncthreads();

            // t = u + A m   (A pre-scaled by 1/sqrt(H); bk-term is softmax-invariant)
            {
                const int part = tid >> 6, cg = tid & 63;
                const float4* Wv = (const float4*)d_AmW;
                float4 acc = make_float4(0.f, 0.f, 0.f, 0.f);
                const int b0 = part * 64;
#pragma unroll 8
                for (int b = b0; b < b0 + 64; b++) {
                    float mb = m_s[b];
                    float4 w = __ldg(&Wv[b * 64 + cg]);
                    acc.x += mb * w.x; acc.y += mb * w.y;
                    acc.z += mb * w.z; acc.w += mb * w.w;
                }
                ((float4*)red_s)[part * 64 + cg] = acc;
                __syncthreads();
                t_s[tid] = __ldg(&d_u[tid]) + red_s[tid] + red_s[Hd + tid]
                         + red_s[2 * Hd + tid] + red_s[3 * Hd + tid];
                __syncthreads();
            }

            // logits[j] = states[n][j] . t   (warp per slot)
            {
                const int w = tid >> 5, lane = tid & 31;
                for (int j = w; j < nval; j += 8) {
                    const float* sp = &d_states[(n * HISTN + j) * Hd];
                    float p = 0.f;
#pragma unroll
                    for (int h = lane; h < Hd; h += 32) p += __ldcg(&sp[h]) * t_s[h];
#pragma unroll
                    for (int o = 16; o; o >>= 1) p += __shfl_down_sync(0xffffffff, p, o);
                    if (lane == 0) lg_s[j] = p;
                }
            }
            __syncthreads();

            if (tid == 0) {   // softmax over <=10 slots
                float mx = lg_s[0];
                for (int j = 1; j < nval; j++) mx = fmaxf(mx, lg_s[j]);
                float sum = 0.f;
                for (int j = 0; j < nval; j++) { float e = __expf(lg_s[j] - mx); att_s[j] = e; sum += e; }
                float inv = 1.0f / sum;
                for (int j = 0; j < nval; j++) att_s[j] *= inv;
            }
            __syncthreads();

            // values[h] = sum_j attn_j * states[n][j][h]
            {
                float vacc = 0.f;
                for (int j = 0; j < nval; j++)
                    vacc += att_s[j] * __ldcg(&d_states[(n * HISTN + j) * Hd + tid]);
                vv_s[tid] = vacc;
            }
            __syncthreads();

            // newstate = values @ Wr_sum + br ; store into ring slot
            {
                const int part = tid >> 6, cg = tid & 63;
                const float4* Wv = (const float4*)d_Wrs;
                float4 acc = make_float4(0.f, 0.f, 0.f, 0.f);
                const int b0 = part * 64;
#pragma unroll 8
                for (int b = b0; b < b0 + 64; b++) {
                    float vb = vv_s[b];
                    float4 w = __ldg(&Wv[b * 64 + cg]);
                    acc.x += vb * w.x; acc.y += vb * w.y;
                    acc.z += vb * w.z; acc.w += vb * w.w;
                }
                ((float4*)red_s)[part * 64 + cg] = acc;
                __syncthreads();
                float ns = __ldg(&br[tid]) + red_s[tid] + red_s[Hd + tid]
                         + red_s[2 * Hd + tid] + red_s[3 * Hd + tid];
                __stcg(&d_states[(n * HISTN + wslot) * Hd + tid], ns);
                cat_s[tid] = ns;
                cat_s[Hd + tid] = m_s[tid];
                __syncthreads();
            }

            // newmessage = [newstate, message] @ Wm + bm  (only if step has children)
            if (i < NMSG) {
                const int part = tid >> 6, cg = tid & 63;
                const float4* Wv = (const float4*)Wm;  // [512][256]
                float4 acc = make_float4(0.f, 0.f, 0.f, 0.f);
                const int b0 = part * 128;
#pragma unroll 8
                for (int b = b0; b < b0 + 128; b++) {
                    float cb = cat_s[b];
                    float4 w = __ldg(&Wv[b * 64 + cg]);
                    acc.x += cb * w.x; acc.y += cb * w.y;
                    acc.z += cb * w.z; acc.w += cb * w.w;
                }
                ((float4*)red_s)[part * 64 + cg] = acc;
                __syncthreads();
                float nm = __ldg(&bm[tid]) + red_s[tid] + red_s[Hd + tid]
                         + red_s[2 * Hd + tid] + red_s[3 * Hd + tid];
                __stcg(&d_msg[i * Md + tid], nm);
            }
            __syncthreads();
        }
        gen = grid_barrier(gen);
    }
}

// ---------------- output head: log_softmax(final @ Wd + bd) ------------------
__global__ void k_final(const float* __restrict__ Wd,
                        const float* __restrict__ bd,
                        float* __restrict__ out) {
    __shared__ float fin[Hd];
    __shared__ float red[Od];
    const int n = blockIdx.x, p = blockIdx.y, t = threadIdx.x;  // 64 threads
    const int fs = d_fslot[n];
    const float* sp = &d_states[(n * HISTN + fs) * Hd];
    for (int h = t; h < Hd; h += Od) fin[h] = sp[h];
    __syncthreads();
    float acc = bd[p * Od + t];
#pragma unroll 4
    for (int h = 0; h < Hd; h++) acc += fin[h] * __ldg(&Wd[(p * Hd + h) * Od + t]);
    red[t] = acc;
    __syncthreads();
    for (int s = 32; s > 0; s >>= 1) { if (t < s) red[t] = fmaxf(red[t], red[t + s]); __syncthreads(); }
    float mx = red[0];
    __syncthreads();
    red[t] = expf(acc - mx);
    __syncthreads();
    for (int s = 32; s > 0; s >>= 1) { if (t < s) red[t] += red[t + s]; __syncthreads(); }
    float lse = mx + logf(red[0]);
    out[(p * Ns + n) * Od + t] = acc - lse;
}

// ---------------- launch -----------------------------------------------------
extern "C" void kernel_launch(void* const* d_in, const int* in_sizes, int n_in,
                              void* d_out, int out_size) {
    const float* xa   = (const float*)d_in[0];
    const int*   nbrs = (const int*)  d_in[1];
    const float* fm   = (const float*)d_in[2];
    const float* We   = (const float*)d_in[3];
    const float* be   = (const float*)d_in[4];
    const float* Wq   = (const float*)d_in[5];
    const float* bq   = (const float*)d_in[6];
    const float* Wk   = (const float*)d_in[7];
    // d_in[8] = bk: provably cancels in softmax (constant logit shift) — unused
    const float* Wr   = (const float*)d_in[9];
    const float* br   = (const float*)d_in[10];
    const float* Wm   = (const float*)d_in[11];
    const float* bm   = (const float*)d_in[12];
    const float* Wd   = (const float*)d_in[13];
    const float* bd   = (const float*)d_in[14];
    float* out = (float*)d_out;

    k_transpose<<<dim3(8, 8), dim3(32, 8)>>>(Wk);
    k_amw<<<Md, Hd>>>(Wq);
    k_u<<<1, Hd>>>(bq);
    k_wrs<<<Hd, Hd>>>(Wr);
    k_init_states<<<Ns, Hd>>>(xa, We, be);
    k_build<<<1, 1024>>>(nbrs);
    k_main<<<GRIDB, 256>>>(fm, br, bm, Wm);
    k_final<<<dim3(Ns, Pd), Od>>>(Wd, bd, out);
}

// round 5
// speedup vs baseline: 2.0031x; 2.0031x over previous
#include <cuda_runtime.h>
#include <math.h>

// Problem constants (fixed shapes for this problem instance)
#define Ns     512
#define DEG    8
#define Fdim   128
#define Hd     256
#define Md     256
#define Od     64
#define Pd     2
#define Sd     64      // num_starts
#define HISTN  10
#define STEPS  5120    // 10*N, all steps active
#define NMSG   632     // steps with children: 64+8*i < 5120
#define NNM    71      // steps whose RAW message is consumed (parents of msg-steps)
#define GRIDB  148

// ---------------- device globals (scratch; no allocation allowed) ------------
__device__ int   d_q[STEPS];
__device__ int   d_occ[STEPS];
__device__ int   d_order[STEPS];
__device__ int   d_loff[STEPS + 1];
__device__ int   d_nlev;
__device__ int   d_fslot[Ns];
__device__ float d_states[Ns * HISTN * Hd];   // 5.24 MB ring buffers
__device__ float d_TTs[Sd * Hd];              // logit vectors for start steps
__device__ float d_TTm[NMSG * Hd];            // logit vector produced by step i for its children
__device__ float d_NM[NNM * Md];              // raw messages (only i<71 need them)
__device__ float d_WkT[Hd * Hd];              // Wk transposed
__device__ float d_AmW[Md * Hd];              // (1/16) Wq @ WkT
__device__ float d_u[Hd];                     // (1/16) Wk @ bq
__device__ float d_Wrs[Hd * Hd];              // sum of 4 row-blocks of Wr
__device__ float d_Wrm[Hd * Md];              // Wrs @ Wm_top
__device__ float d_TTW[2 * Hd * Hd];          // [WrmA ; WmbA] stacked (512 x 256)
__device__ float d_brm[Md];                   // br @ Wm_top + bm
__device__ float d_bTT[Hd];                   // brm @ AmW + u
__device__ unsigned d_bcnt = 0;
__device__ unsigned d_bgen = 0;

__device__ __forceinline__ void fma4(float4& a, float s, const float4 w) {
    a.x += s * w.x; a.y += s * w.y; a.z += s * w.z; a.w += s * w.w;
}

// ---------------- grid barrier -----------------------------------------------
__device__ __forceinline__ unsigned grid_barrier(unsigned gen) {
    __syncthreads();
    if (threadIdx.x == 0) {
        __threadfence();
        if (atomicAdd(&d_bcnt, 1u) == gridDim.x - 1) {
            d_bcnt = 0;
            __threadfence();
            *((volatile unsigned*)&d_bgen) = gen + 1;
        } else {
            while (*((volatile unsigned*)&d_bgen) != gen + 1) __nanosleep(32);
        }
        __threadfence();
    }
    __syncthreads();
    return gen + 1;
}

// ---------------- schedule builder (single block, smem) ----------------------
// launch #1 (independent of everything else)
__global__ __launch_bounds__(1024) void k_build(const int* __restrict__ neighbors) {
    extern __shared__ int sh[];
    int* q     = sh;                 // STEPS
    int* prevs = q + STEPS;          // STEPS
    int* lvl   = prevs + STEPS;      // STEPS
    int* nb    = lvl + STEPS;        // Ns*DEG
    int* hist  = nb + Ns * DEG;      // STEPS+1
    __shared__ int s_changed, s_maxl;
    const int tid = threadIdx.x;

    for (int x = tid; x < Ns * DEG; x += 1024) nb[x] = neighbors[x];
    if (tid < Sd) q[tid] = tid;
    __syncthreads();

    // node sequence: q[i] = nbrs[q[(i-64)>>3]][(i-64)&7]  (3 doubling rounds)
    int v = Sd;
    while (v < STEPS) {
        int nv = min(STEPS, Sd + DEG * v);
        for (int x = v + tid; x < nv; x += 1024)
            q[x] = nb[q[(x - Sd) >> 3] * DEG + ((x - Sd) & 7)];
        __syncthreads();
        v = nv;
    }

    // per-node occurrence scan (thread = node; broadcast smem reads)
    if (tid < Ns) {
        int cnt = 0, last = -1;
        for (int ii = 0; ii < STEPS; ii++) {
            if (q[ii] == tid) { d_occ[ii] = cnt; prevs[ii] = last; last = ii; cnt++; }
        }
        d_fslot[tid] = cnt % HISTN;
    }
    __syncthreads();

    // exact levels: monotone fixpoint entirely in smem (benign races, monotone)
    for (int x = tid; x < STEPS; x += 1024) lvl[x] = 0;
    __syncthreads();
    while (true) {
        if (tid == 0) s_changed = 0;
        __syncthreads();
        for (int x = tid; x < STEPS; x += 1024) {
            int nl = 0;
            if (x >= Sd) nl = lvl[(x - Sd) >> 3] + 1;
            int pv = prevs[x];
            if (pv >= 0) { int t2 = lvl[pv] + 1; if (t2 > nl) nl = t2; }
            if (nl > lvl[x]) { lvl[x] = nl; s_changed = 1; }
        }
        __syncthreads();
        int ch = s_changed;
        __syncthreads();
        if (!ch) break;
    }

    if (tid == 0) s_maxl = 0;
    __syncthreads();
    { int lm = 0;
      for (int x = tid; x < STEPS; x += 1024) lm = max(lm, lvl[x]);
      atomicMax(&s_maxl, lm); }
    __syncthreads();
    const int nlev = s_maxl + 1;

    // counting sort by level (smem atomics)
    for (int x = tid; x <= STEPS; x += 1024) hist[x] = 0;
    __syncthreads();
    for (int x = tid; x < STEPS; x += 1024) atomicAdd(&hist[lvl[x]], 1);
    __syncthreads();
    if (tid == 0) {
        int run = 0;
        for (int L = 0; L < nlev; L++) { int cc = hist[L]; hist[L] = run; d_loff[L] = run; run += cc; }
        d_loff[nlev] = run;
        d_nlev = nlev;
    }
    __syncthreads();
    for (int x = tid; x < STEPS; x += 1024) {
        int p = atomicAdd(&hist[lvl[x]], 1);
        d_order[p] = x;
        d_q[x] = q[x];
    }
}

// ---------------- prep kernel 1 (independent pieces) --------------------------
// launch #2
__global__ __launch_bounds__(256) void k_prep1(
    const float* __restrict__ Wk, const float* __restrict__ Wr,
    const float* __restrict__ xa, const float* __restrict__ We,
    const float* __restrict__ be, const float* __restrict__ br,
    const float* __restrict__ Wm, const float* __restrict__ bm) {
    const int b = blockIdx.x, tid = threadIdx.x;
    if (b < 64) {                       // WkT[x][h'] = Wk[h'][x]
        __shared__ float tile[32][33];
        const int x0 = (b & 7) * 32, y0 = (b >> 3) * 32;
        const int lx = tid & 31, ly = tid >> 5;
        for (int i = ly; i < 32; i += 8) tile[i][lx] = Wk[(y0 + i) * Hd + x0 + lx];
        __syncthreads();
        for (int i = ly; i < 32; i += 8) d_WkT[(x0 + i) * Hd + y0 + lx] = tile[lx][i];
    } else if (b < 320) {               // Wrs = sum of 4 row-blocks of Wr
        int x = b - 64;
        d_Wrs[x * Hd + tid] = Wr[x * Hd + tid] + Wr[(Hd + x) * Hd + tid]
                            + Wr[(2 * Hd + x) * Hd + tid] + Wr[(3 * Hd + x) * Hd + tid];
    } else if (b < 832) {               // encoded = xa @ We + be -> states slot 0
        int n = b - 320;
        __shared__ float xs[Fdim];
        if (tid < Fdim) xs[tid] = xa[n * Fdim + tid];
        __syncthreads();
        float acc = be[tid];
#pragma unroll 4
        for (int f = 0; f < Fdim; f++) acc += xs[f] * We[f * Hd + tid];
        d_states[n * HISTN * Hd + tid] = acc;
    } else {                            // brm = br @ Wm_top + bm
        __shared__ float brs[Hd];
        brs[tid] = br[tid];
        __syncthreads();
        float acc = bm[tid];
#pragma unroll 4
        for (int h = 0; h < Hd; h++) acc += brs[h] * Wm[h * Md + tid];
        d_brm[tid] = acc;
    }
}

// 8-row x 256-col GEMM tile: O[8,256] = L[8,256] @ R[256,256] * scale (+ bias)
__device__ void gemm8(const float* __restrict__ L, const float* __restrict__ R,
                      float* __restrict__ O, float scale, const float* __restrict__ bias) {
    __shared__ float Ls[8 * 256];
    const int tid = threadIdx.x;
    for (int idx = tid; idx < 8 * 256; idx += 256) Ls[idx] = __ldcg(&L[idx]);
    __syncthreads();
    float a0=0,a1=0,a2=0,a3=0,a4=0,a5=0,a6=0,a7=0;
#pragma unroll 4
    for (int k = 0; k < 256; k++) {
        float rk = __ldcg(&R[k * 256 + tid]);
        a0 += Ls[0*256+k]*rk; a1 += Ls[1*256+k]*rk; a2 += Ls[2*256+k]*rk; a3 += Ls[3*256+k]*rk;
        a4 += Ls[4*256+k]*rk; a5 += Ls[5*256+k]*rk; a6 += Ls[6*256+k]*rk; a7 += Ls[7*256+k]*rk;
    }
    float bv = bias ? __ldcg(&bias[tid]) : 0.f;
    O[0*256+tid]=a0*scale+bv; O[1*256+tid]=a1*scale+bv; O[2*256+tid]=a2*scale+bv; O[3*256+tid]=a3*scale+bv;
    O[4*256+tid]=a4*scale+bv; O[5*256+tid]=a5*scale+bv; O[6*256+tid]=a6*scale+bv; O[7*256+tid]=a7*scale+bv;
    __syncthreads();
}

// ---------------- prep kernel 2 (2 stages, internal grid barrier) ------------
// launch #3, grid = 73 blocks x 256 threads
__global__ __launch_bounds__(256) void k_prep2(const float* __restrict__ Wq,
                                               const float* __restrict__ bq,
                                               const float* __restrict__ Wk,
                                               const float* __restrict__ Wm,
                                               const float* __restrict__ fm) {
    const int b = blockIdx.x, tid = threadIdx.x;
    unsigned gen = *((volatile unsigned*)&d_bgen);
    // ---- stage 1: AmW = (1/16) Wq @ WkT ; Wrm = Wrs @ Wm_top ; u = (1/16) Wk @ bq
    if (b < 32)      gemm8(Wq + b * 2048, d_WkT, d_AmW + b * 2048, 0.0625f, 0);
    else if (b < 64) gemm8(d_Wrs + (b - 32) * 2048, Wm, d_Wrm + (b - 32) * 2048, 1.f, 0);
    else if (b == 64) {
        __shared__ float bqs[Hd];
        bqs[tid] = bq[tid];
        __syncthreads();
        float acc = 0.f;
#pragma unroll 4
        for (int h = 0; h < Hd; h++) acc += Wk[tid * Hd + h] * bqs[h];
        d_u[tid] = acc * 0.0625f;
    }
    gen = grid_barrier(gen);
    // ---- stage 2: TTW = [Wrm@AmW ; Wm_bot@AmW] ; TTs = fm@AmW + u ; bTT
    if (b < 32)      gemm8(d_Wrm + b * 2048, d_AmW, d_TTW + b * 2048, 1.f, 0);
    else if (b < 64) gemm8(Wm + Hd * Md + (b - 32) * 2048, d_AmW, d_TTW + Hd * Hd + (b - 32) * 2048, 1.f, 0);
    else if (b < 72) gemm8(fm + (b - 64) * 2048, d_AmW, d_TTs + (b - 64) * 2048, 1.f, d_u);
    else {
        float acc = __ldcg(&d_u[tid]);
#pragma unroll 4
        for (int y = 0; y < Md; y++) acc += __ldcg(&d_brm[y]) * __ldcg(&d_AmW[y * Hd + tid]);
        d_bTT[tid] = acc;
    }
}

// ---------------- main persistent level-parallel kernel ----------------------
// launch #4 (ncu -s 5 -c 1 captures this one)
__global__ __launch_bounds__(512, 1) void k_main(const float* __restrict__ fm,
                                                 const float* __restrict__ br,
                                                 const float* __restrict__ Wm,
                                                 const float* __restrict__ bm) {
    __shared__ float t_s[Hd], m_s[Md], vv_s[Hd], cat_s[Hd + Md];
    __shared__ float st_s[HISTN][Hd];    // staged history (10 KB)
    __shared__ float red_s[2048];        // reduction space (8 KB)
    __shared__ float lg_s[HISTN], att_s[HISTN];
    __shared__ int   info_s[3];
    const int tid = threadIdx.x;

    unsigned gen = *((volatile unsigned*)&d_bgen);
    const int nlev = d_nlev;

    for (int L = 0; L < nlev; L++) {
        const int lo = d_loff[L], hi = d_loff[L + 1];
        for (int pos = lo + blockIdx.x; pos < hi; pos += gridDim.x) {
            if (tid == 0) {
                int i = d_order[pos];
                info_s[0] = i; info_s[1] = d_q[i]; info_s[2] = d_occ[i];
            }
            __syncthreads();
            const int i = info_s[0], n = info_s[1], oc = info_s[2];
            const int c = oc + 1;
            const int nval  = (c < HISTN) ? c : HISTN;
            const int wslot = c % HISTN;
            const bool has_tt = (i < NMSG);
            const bool has_nm = (i < NNM);

            // ---- load logit vector t (from parent) and raw message m ----
            if (tid < Hd) {
                t_s[tid] = (i < Sd) ? __ldg(&d_TTs[i * Hd + tid])
                                    : __ldcg(&d_TTm[((i - Sd) >> 3) * Hd + tid]);
            } else if (has_tt) {
                const int h = tid - Hd;
                m_s[h] = (i < Sd) ? __ldg(&fm[i * Md + h])
                                  : __ldcg(&d_NM[((i - Sd) >> 3) * Md + h]);
            }
            __syncthreads();

            // ---- logits_j = states[n][j] . t  (warp per slot; stage states) ----
            {
                const int w = tid >> 5, lane = tid & 31;
                if (w < nval) {
                    const float* sp = &d_states[(n * HISTN + w) * Hd];
                    float p = 0.f;
#pragma unroll
                    for (int h0 = 0; h0 < 8; h0++) {
                        const int h = h0 * 32 + lane;
                        float sv = __ldcg(&sp[h]);
                        st_s[w][h] = sv;
                        p += sv * t_s[h];
                    }
#pragma unroll
                    for (int o = 16; o; o >>= 1) p += __shfl_down_sync(0xffffffffu, p, o);
                    if (lane == 0) lg_s[w] = p;
                }
            }
            __syncthreads();

            if (tid == 0) {   // softmax over <=10 slots
                float mx = lg_s[0];
                for (int j = 1; j < nval; j++) mx = fmaxf(mx, lg_s[j]);
                float sum = 0.f;
                for (int j = 0; j < nval; j++) { float e = __expf(lg_s[j] - mx); att_s[j] = e; sum += e; }
                float inv = 1.0f / sum;
                for (int j = 0; j < nval; j++) att_s[j] *= inv;
            }
            __syncthreads();

            // ---- values ----
            if (tid < Hd) {
                float vacc = 0.f;
                for (int j = 0; j < nval; j++) vacc += att_s[j] * st_s[j][tid];
                vv_s[tid] = vacc;
            }
            __syncthreads();

            // ---- concurrent matvecs: ns = v@Wrs (threads 0-255, 4-way K),
            //      TT = [v;m]@TTW (threads 256-511, 4-way K over 512) ----
            if (tid < Hd) {
                const int cg = tid & 63, part = tid >> 6;
                const float4* Wv = (const float4*)d_Wrs;
                float4 acc = make_float4(0.f, 0.f, 0.f, 0.f);
                const int b0 = part * 64;
#pragma unroll 8
                for (int bb = b0; bb < b0 + 64; bb++)
                    fma4(acc, vv_s[bb], __ldg(&Wv[bb * 64 + cg]));
                ((float4*)red_s)[part * 64 + cg] = acc;
            } else if (has_tt) {
                const int t2 = tid - Hd, cg = t2 & 63, part = t2 >> 6;
                const float4* Wv = (const float4*)d_TTW;
                float4 acc = make_float4(0.f, 0.f, 0.f, 0.f);
                const int b0 = part * 128;
                if (part < 2) {
#pragma unroll 8
                    for (int bb = b0; bb < b0 + 128; bb++)
                        fma4(acc, vv_s[bb], __ldg(&Wv[bb * 64 + cg]));
                } else {
#pragma unroll 8
                    for (int bb = b0; bb < b0 + 128; bb++)
                        fma4(acc, m_s[bb - Hd], __ldg(&Wv[bb * 64 + cg]));
                }
                ((float4*)red_s)[256 + part * 64 + cg] = acc;
            }
            __syncthreads();

            // ---- reduce + write ns / TT ----
            if (tid < Hd) {
                float ns = __ldg(&br[tid]) + red_s[tid] + red_s[256 + tid]
                         + red_s[512 + tid] + red_s[768 + tid];
                __stcg(&d_states[(n * HISTN + wslot) * Hd + tid], ns);
                if (has_nm) cat_s[tid] = ns;
            } else if (has_tt) {
                const int t2 = tid - Hd;
                float tt = __ldg(&d_bTT[t2]) + red_s[1024 + t2] + red_s[1280 + t2]
                         + red_s[1536 + t2] + red_s[1792 + t2];
                __stcg(&d_TTm[i * Hd + t2], tt);
                if (has_nm) cat_s[Hd + t2] = m_s[t2];
            }
            __syncthreads();

            // ---- raw message (only 71 steps): NM = [ns;m] @ Wm + bm ----
            if (has_nm) {
                const int cg = tid & 63, part = tid >> 6;   // 8 parts x 64 K each
                const float4* Wv = (const float4*)Wm;
                float4 acc = make_float4(0.f, 0.f, 0.f, 0.f);
                const int b0 = part * 64;
#pragma unroll 8
                for (int bb = b0; bb < b0 + 64; bb++)
                    fma4(acc, cat_s[bb], __ldg(&Wv[bb * 64 + cg]));
                ((float4*)red_s)[part * 64 + cg] = acc;
                __syncthreads();
                if (tid < Hd) {
                    float nm = __ldg(&bm[tid]);
#pragma unroll
                    for (int p = 0; p < 8; p++) nm += red_s[p * 256 + tid];
                    __stcg(&d_NM[i * Md + tid], nm);
                }
                __syncthreads();
            }
        }
        gen = grid_barrier(gen);
    }
}

// ---------------- output head: log_softmax(final @ Wd + bd) ------------------
// launch #5
__global__ void k_final(const float* __restrict__ Wd,
                        const float* __restrict__ bd,
                        float* __restrict__ out) {
    __shared__ float fin[Hd];
    __shared__ float red[Od];
    const int n = blockIdx.x, p = blockIdx.y, t = threadIdx.x;  // 64 threads
    const int fs = d_fslot[n];
    const float* sp = &d_states[(n * HISTN + fs) * Hd];
    for (int h = t; h < Hd; h += Od) fin[h] = sp[h];
    __syncthreads();
    float acc = bd[p * Od + t];
#pragma unroll 4
    for (int h = 0; h < Hd; h++) acc += fin[h] * __ldg(&Wd[(p * Hd + h) * Od + t]);
    red[t] = acc;
    __syncthreads();
    for (int s = 32; s > 0; s >>= 1) { if (t < s) red[t] = fmaxf(red[t], red[t + s]); __syncthreads(); }
    float mx = red[0];
    __syncthreads();
    red[t] = expf(acc - mx);
    __syncthreads();
    for (int s = 32; s > 0; s >>= 1) { if (t < s) red[t] += red[t + s]; __syncthreads(); }
    float lse = mx + logf(red[0]);
    out[(p * Ns + n) * Od + t] = acc - lse;
}

// ---------------- launch -----------------------------------------------------
extern "C" void kernel_launch(void* const* d_in, const int* in_sizes, int n_in,
                              void* d_out, int out_size) {
    const float* xa   = (const float*)d_in[0];
    const int*   nbrs = (const int*)  d_in[1];
    const float* fm   = (const float*)d_in[2];
    const float* We   = (const float*)d_in[3];
    const float* be   = (const float*)d_in[4];
    const float* Wq   = (const float*)d_in[5];
    const float* bq   = (const float*)d_in[6];
    const float* Wk   = (const float*)d_in[7];
    // d_in[8] = bk: cancels in softmax (constant logit shift) — unused
    const float* Wr   = (const float*)d_in[9];
    const float* br   = (const float*)d_in[10];
    const float* Wm   = (const float*)d_in[11];
    const float* bm   = (const float*)d_in[12];
    const float* Wd   = (const float*)d_in[13];
    const float* bd   = (const float*)d_in[14];
    float* out = (float*)d_out;

    // 96 KB dynamic smem for the builder (idempotent; not a stream op, capture-safe)
    const int BUILD_SMEM = (3 * STEPS + Ns * DEG + STEPS + 1) * (int)sizeof(int);
    cudaFuncSetAttribute(k_build, cudaFuncAttributeMaxDynamicSharedMemorySize, BUILD_SMEM);

    k_build<<<1, 1024, BUILD_SMEM>>>(nbrs);                 // our launch #1
    k_prep1<<<833, 256>>>(Wk, Wr, xa, We, be, br, Wm, bm);  // #2
    k_prep2<<<73, 256>>>(Wq, bq, Wk, Wm, fm);               // #3
    k_main<<<GRIDB, 512>>>(fm, br, Wm, bm);                 // #4  <- ncu target
    k_final<<<dim3(Ns, Pd), Od>>>(Wd, bd, out);             // #5
}

// round 10
// speedup vs baseline: 2.5814x; 1.2887x over previous
#include <cuda_runtime.h>
#include <math.h>

// Problem constants (fixed shapes for this problem instance)
#define Ns     512
#define DEG    8
#define Fdim   128
#define Hd     256
#define Md     256
#define Od     64
#define Pd     2
#define Sd     64      // num_starts
#define HISTN  10
#define STEPS  5120    // 10*N, all steps active
#define NMSG   632     // steps with children: 64+8*i < 5120
#define NNM    71      // steps whose RAW message is consumed (parents of msg-steps)
#define GRIDB  148
#define CAPS   24      // per-node occurrence scratch capacity (fallback if exceeded)

// ---------------- device globals (scratch; no allocation allowed) ------------
__device__ int   d_q[STEPS];
__device__ int   d_occ[STEPS];
__device__ int   d_prevs[STEPS];
__device__ int   d_order[STEPS];
__device__ int   d_fslot[Ns];
__device__ int   d_flagT[STEPS];              // 0 none, 1 TT done, 2 TT+NM done
__device__ int   d_flagS[STEPS];              // state write done
__device__ int   d_pop;                       // dynamic work ticket
__device__ float d_states[Ns * HISTN * Hd];   // 5.24 MB ring buffers
__device__ float d_TTs[Sd * Hd];              // logit vectors for start steps
__device__ float d_TTm[NMSG * Hd];            // logit vector produced by step i for its children
__device__ float d_NM[NNM * Md];              // raw messages (only i<71 need them)
__device__ float d_WkT[Hd * Hd];              // Wk transposed
__device__ float d_AmW[Md * Hd];              // (1/16) Wq @ WkT
__device__ float d_u[Hd];                     // (1/16) Wk @ bq
__device__ float d_Wrs[Hd * Hd];              // sum of 4 row-blocks of Wr
__device__ float d_Wrm[Hd * Md];              // Wrs @ Wm_top
__device__ float d_TTW[2 * Hd * Hd];          // [WrmA ; WmbA] stacked (512 x 256)
__device__ float d_brm[Md];                   // br @ Wm_top + bm
__device__ float d_bTT[Hd];                   // brm @ AmW + u
__device__ unsigned d_bcnt = 0;
__device__ unsigned d_bgen = 0;

__device__ __forceinline__ void fma4(float4& a, float s, const float4 w) {
    a.x += s * w.x; a.y += s * w.y; a.z += s * w.z; a.w += s * w.w;
}

// ---------------- grid barrier -----------------------------------------------
__device__ __forceinline__ unsigned grid_barrier(unsigned gen) {
    __syncthreads();
    if (threadIdx.x == 0) {
        __threadfence();
        if (atomicAdd(&d_bcnt, 1u) == gridDim.x - 1) {
            d_bcnt = 0;
            __threadfence();
            *((volatile unsigned*)&d_bgen) = gen + 1;
        } else {
            while (*((volatile unsigned*)&d_bgen) != gen + 1) __nanosleep(32);
        }
        __threadfence();
    }
    __syncthreads();
    return gen + 1;
}

// ---------------- schedule builder (single block, all smem) -------------------
// launch #1
__global__ __launch_bounds__(1024) void k_build(const int* __restrict__ neighbors) {
    extern __shared__ int sh[];
    int* q     = sh;                     // STEPS
    int* prevs = q + STEPS;              // STEPS
    int* lvl   = prevs + STEPS;          // STEPS
    int* nb    = lvl + STEPS;            // Ns*DEG
    int* scr   = nb + Ns * DEG;          // Ns*CAPS (aliased later as hist)
    int* cnt   = scr + Ns * CAPS;        // Ns
    int* hist  = scr;                    // alias (reused after occurrence phase)
    __shared__ int s_changed, s_maxl;
    const int tid = threadIdx.x;

    for (int x = tid; x < Ns * DEG; x += 1024) nb[x] = neighbors[x];
    for (int x = tid; x < Ns; x += 1024) cnt[x] = 0;
    if (tid < Sd) q[tid] = tid;
    __syncthreads();

    // node sequence: q[i] = nbrs[q[(i-64)>>3]][(i-64)&7]  (3 doubling rounds)
    int v = Sd;
    while (v < STEPS) {
        int nv = min(STEPS, Sd + DEG * v);
        for (int x = v + tid; x < nv; x += 1024)
            q[x] = nb[q[(x - Sd) >> 3] * DEG + ((x - Sd) & 7)];
        __syncthreads();
        v = nv;
    }

    // occurrence lists: atomic append + per-node insertion sort (exact fallback)
    for (int x = tid; x < STEPS; x += 1024) {
        int n = q[x];
        int s = atomicAdd(&cnt[n], 1);
        if (s < CAPS) scr[n * CAPS + s] = x;
    }
    __syncthreads();
    if (tid < Ns) {
        const int n = tid;
        const int c = cnt[n];
        d_fslot[n] = c % HISTN;
        if (c <= CAPS) {
            int* s = &scr[n * CAPS];
            for (int k = 1; k < c; k++) {           // insertion sort ascending
                int vv = s[k], j = k - 1;
                while (j >= 0 && s[j] > vv) { s[j + 1] = s[j]; j--; }
                s[j + 1] = vv;
            }
            int last = -1;
            for (int k = 0; k < c; k++) {
                int idx = s[k];
                d_occ[idx] = k;
                prevs[idx] = last;
                last = idx;
            }
        } else {                                     // rare exact fallback
            int k = 0, last = -1;
            for (int ii = 0; ii < STEPS; ii++) {
                if (q[ii] == n) { d_occ[ii] = k; prevs[ii] = last; last = ii; k++; }
            }
        }
    }
    __syncthreads();

    // exact levels: chunk-ordered monotone fixpoint (deps of chunk k>=1 resolved)
    for (int x = tid; x < STEPS; x += 1024) lvl[x] = 0;
    __syncthreads();
    for (int c0 = 0; c0 < STEPS; c0 += 1024) {
        const int x = c0 + tid;
        while (true) {
            if (tid == 0) s_changed = 0;
            __syncthreads();
            int nl = 0;
            if (x >= Sd) nl = lvl[(x - Sd) >> 3] + 1;
            int pv = prevs[x];
            if (pv >= 0) { int t2 = lvl[pv] + 1; if (t2 > nl) nl = t2; }
            if (nl > lvl[x]) { lvl[x] = nl; s_changed = 1; }
            __syncthreads();
            int ch = s_changed;
            __syncthreads();
            if (!ch) break;
        }
    }

    if (tid == 0) s_maxl = 0;
    __syncthreads();
    { int lm = 0;
      for (int x = tid; x < STEPS; x += 1024) lm = max(lm, lvl[x]);
      atomicMax(&s_maxl, lm); }
    __syncthreads();
    const int nlev = s_maxl + 1;

    // counting sort by level -> d_order (hist aliases scr; occurrence phase done)
    for (int x = tid; x <= STEPS; x += 1024) hist[x] = 0;
    __syncthreads();
    for (int x = tid; x < STEPS; x += 1024) atomicAdd(&hist[lvl[x]], 1);
    __syncthreads();
    if (tid == 0) {
        int run = 0;
        for (int L = 0; L < nlev; L++) { int cc = hist[L]; hist[L] = run; run += cc; }
    }
    __syncthreads();
    for (int x = tid; x < STEPS; x += 1024) {
        int p = atomicAdd(&hist[lvl[x]], 1);
        d_order[p] = x;
        d_q[x] = q[x];
        d_prevs[x] = prevs[x];
    }
}

// ---------------- prep kernel 1 (independent pieces + flag reset) -------------
// launch #2, grid = 853 x 256
__global__ __launch_bounds__(256) void k_prep1(
    const float* __restrict__ Wk, const float* __restrict__ Wr,
    const float* __restrict__ xa, const float* __restrict__ We,
    const float* __restrict__ be, const float* __restrict__ br,
    const float* __restrict__ Wm, const float* __restrict__ bm) {
    const int b = blockIdx.x, tid = threadIdx.x;
    if (b < 64) {                       // WkT[x][h'] = Wk[h'][x]
        __shared__ float tile[32][33];
        const int x0 = (b & 7) * 32, y0 = (b >> 3) * 32;
        const int lx = tid & 31, ly = tid >> 5;
        for (int i = ly; i < 32; i += 8) tile[i][lx] = Wk[(y0 + i) * Hd + x0 + lx];
        __syncthreads();
        for (int i = ly; i < 32; i += 8) d_WkT[(x0 + i) * Hd + y0 + lx] = tile[lx][i];
    } else if (b < 320) {               // Wrs = sum of 4 row-blocks of Wr
        int x = b - 64;
        d_Wrs[x * Hd + tid] = Wr[x * Hd + tid] + Wr[(Hd + x) * Hd + tid]
                            + Wr[(2 * Hd + x) * Hd + tid] + Wr[(3 * Hd + x) * Hd + tid];
    } else if (b < 832) {               // encoded = xa @ We + be -> states slot 0
        int n = b - 320;
        __shared__ float xs[Fdim];
        if (tid < Fdim) xs[tid] = xa[n * Fdim + tid];
        __syncthreads();
        float acc = be[tid];
#pragma unroll 4
        for (int f = 0; f < Fdim; f++) acc += xs[f] * We[f * Hd + tid];
        d_states[n * HISTN * Hd + tid] = acc;
    } else if (b == 832) {              // brm = br @ Wm_top + bm
        __shared__ float brs[Hd];
        brs[tid] = br[tid];
        __syncthreads();
        float acc = bm[tid];
#pragma unroll 4
        for (int h = 0; h < Hd; h++) acc += brs[h] * Wm[h * Md + tid];
        d_brm[tid] = acc;
    } else {                            // zero dataflow flags + ticket
        int idx = (b - 833) * 256 + tid;
        if (idx < STEPS) { d_flagT[idx] = 0; d_flagS[idx] = 0; }
        if (b == 833 && tid == 0) d_pop = 0;
    }
}

// 8-row x 256-col GEMM tile: O[8,256] = L[8,256] @ R[256,256] * scale (+ bias)
__device__ void gemm8(const float* __restrict__ L, const float* __restrict__ R,
                      float* __restrict__ O, float scale, const float* __restrict__ bias) {
    __shared__ float Ls[8 * 256];
    const int tid = threadIdx.x;
    for (int idx = tid; idx < 8 * 256; idx += 256) Ls[idx] = __ldcg(&L[idx]);
    __syncthreads();
    float a0=0,a1=0,a2=0,a3=0,a4=0,a5=0,a6=0,a7=0;
#pragma unroll 4
    for (int k = 0; k < 256; k++) {
        float rk = __ldcg(&R[k * 256 + tid]);
        a0 += Ls[0*256+k]*rk; a1 += Ls[1*256+k]*rk; a2 += Ls[2*256+k]*rk; a3 += Ls[3*256+k]*rk;
        a4 += Ls[4*256+k]*rk; a5 += Ls[5*256+k]*rk; a6 += Ls[6*256+k]*rk; a7 += Ls[7*256+k]*rk;
    }
    float bv = bias ? __ldcg(&bias[tid]) : 0.f;
    O[0*256+tid]=a0*scale+bv; O[1*256+tid]=a1*scale+bv; O[2*256+tid]=a2*scale+bv; O[3*256+tid]=a3*scale+bv;
    O[4*256+tid]=a4*scale+bv; O[5*256+tid]=a5*scale+bv; O[6*256+tid]=a6*scale+bv; O[7*256+tid]=a7*scale+bv;
    __syncthreads();
}

// ---------------- prep kernel 2 (2 stages, internal grid barrier) ------------
// launch #3, grid = 73 x 256
__global__ __launch_bounds__(256) void k_prep2(const float* __restrict__ Wq,
                                               const float* __restrict__ bq,
                                               const float* __restrict__ Wk,
                                               const float* __restrict__ Wm,
                                               const float* __restrict__ fm) {
    const int b = blockIdx.x, tid = threadIdx.x;
    unsigned gen = *((volatile unsigned*)&d_bgen);
    // ---- stage 1: AmW = (1/16) Wq @ WkT ; Wrm = Wrs @ Wm_top ; u = (1/16) Wk @ bq
    if (b < 32)      gemm8(Wq + b * 2048, d_WkT, d_AmW + b * 2048, 0.0625f, 0);
    else if (b < 64) gemm8(d_Wrs + (b - 32) * 2048, Wm, d_Wrm + (b - 32) * 2048, 1.f, 0);
    else if (b == 64) {
        __shared__ float bqs[Hd];
        bqs[tid] = bq[tid];
        __syncthreads();
        float acc = 0.f;
#pragma unroll 4
        for (int h = 0; h < Hd; h++) acc += Wk[tid * Hd + h] * bqs[h];
        d_u[tid] = acc * 0.0625f;
    }
    gen = grid_barrier(gen);
    // ---- stage 2: TTW = [Wrm@AmW ; Wm_bot@AmW] ; TTs = fm@AmW + u ; bTT
    if (b < 32)      gemm8(d_Wrm + b * 2048, d_AmW, d_TTW + b * 2048, 1.f, 0);
    else if (b < 64) gemm8(Wm + Hd * Md + (b - 32) * 2048, d_AmW, d_TTW + Hd * Hd + (b - 32) * 2048, 1.f, 0);
    else if (b < 72) gemm8(fm + (b - 64) * 2048, d_AmW, d_TTs + (b - 64) * 2048, 1.f, d_u);
    else {
        float acc = __ldcg(&d_u[tid]);
#pragma unroll 4
        for (int y = 0; y < Md; y++) acc += __ldcg(&d_brm[y]) * __ldcg(&d_AmW[y * 256 + tid]);
        d_bTT[tid] = acc;
    }
}

// ---------------- main persistent dataflow kernel (+ fused output head) ------
// launch #4 (ncu -s 5 -c 1 captures this one)
__global__ __launch_bounds__(512, 1) void k_main(const float* __restrict__ fm,
                                                 const float* __restrict__ br,
                                                 const float* __restrict__ Wm,
                                                 const float* __restrict__ bm,
                                                 const float* __restrict__ Wd,
                                                 const float* __restrict__ bd,
                                                 float* __restrict__ out) {
    __shared__ float t_s[Hd], m_s[Md], vv_s[Hd], cat_s[Hd + Md];
    __shared__ float st_s[HISTN][Hd];    // staged history (10 KB)
    __shared__ float red_s[2048];        // reduction space (8 KB)
    __shared__ float lg_s[HISTN], att_s[HISTN];
    __shared__ int   info_s[5];
    const int tid = threadIdx.x;

    unsigned gen = *((volatile unsigned*)&d_bgen);
    volatile int* flagT = (volatile int*)d_flagT;
    volatile int* flagS = (volatile int*)d_flagS;

    while (true) {
        // ---- pop next step (dynamic ticket over level-sorted order) ----
        if (tid == 0) {
            int pos = atomicAdd(&d_pop, 1);
            info_s[3] = pos;
            if (pos < STEPS) {
                int i = d_order[pos];
                info_s[0] = i; info_s[1] = d_q[i]; info_s[2] = d_occ[i];
                info_s[4] = d_prevs[i];
            }
        }
        __syncthreads();
        if (info_s[3] >= STEPS) break;
        const int i = info_s[0], n = info_s[1], oc = info_s[2], pv = info_s[4];
        const int c = oc + 1;
        const int nval  = (c < HISTN) ? c : HISTN;
        const int wslot = c % HISTN;
        const bool has_tt = (i < NMSG);
        const bool has_nm = (i < NNM);

        // ---- wait on deps (two pollers in parallel, HW-sleep backoff) ----
        if (tid == 0) {
            if (pv >= 0) { while (flagS[pv] == 0) __nanosleep(20); }
            __threadfence();
        } else if (tid == 32 && i >= Sd) {
            const int par = (i - Sd) >> 3;
            const int need = has_tt ? 2 : 1;
            while (flagT[par] < need) __nanosleep(20);
            __threadfence();
        }
        __syncthreads();

        // ---- load logit vector t (from parent) and raw message m ----
        if (tid < Hd) {
            t_s[tid] = (i < Sd) ? __ldg(&d_TTs[i * Hd + tid])
                                : __ldcg(&d_TTm[((i - Sd) >> 3) * Hd + tid]);
        } else if (has_tt) {
            const int h = tid - Hd;
            m_s[h] = (i < Sd) ? __ldg(&fm[i * Md + h])
                              : __ldcg(&d_NM[((i - Sd) >> 3) * Md + h]);
        }
        __syncthreads();

        // ---- logits_j = states[n][j] . t  (warp per slot; stage states) ----
        {
            const int w = tid >> 5, lane = tid & 31;
            if (w < nval) {
                const float* sp = &d_states[(n * HISTN + w) * Hd];
                float p = 0.f;
#pragma unroll
                for (int h0 = 0; h0 < 8; h0++) {
                    const int h = h0 * 32 + lane;
                    float sv = __ldcg(&sp[h]);
                    st_s[w][h] = sv;
                    p += sv * t_s[h];
                }
#pragma unroll
                for (int o = 16; o; o >>= 1) p += __shfl_down_sync(0xffffffffu, p, o);
                if (lane == 0) lg_s[w] = p;
            }
        }
        __syncthreads();

        // ---- softmax over <=10 slots (warp-parallel, warp 0) ----
        if (tid < 32) {
            float lv = (tid < nval) ? lg_s[tid] : -3.4e38f;
            float mx = lv;
#pragma unroll
            for (int o = 16; o; o >>= 1) mx = fmaxf(mx, __shfl_xor_sync(0xffffffffu, mx, o));
            float e = (tid < nval) ? __expf(lv - mx) : 0.f;
            float sum = e;
#pragma unroll
            for (int o = 16; o; o >>= 1) sum += __shfl_xor_sync(0xffffffffu, sum, o);
            if (tid < nval) att_s[tid] = e / sum;
        }
        __syncthreads();

        // ---- values ----
        if (tid < Hd) {
            float vacc = 0.f;
            for (int j = 0; j < nval; j++) vacc += att_s[j] * st_s[j][tid];
            vv_s[tid] = vacc;
        }
        __syncthreads();

        // ---- concurrent matvecs: ns = v@Wrs (threads 0-255, 4-way K),
        //      TT = [v;m]@TTW (threads 256-511, 4-way K over 512) ----
        if (tid < Hd) {
            const int cg = tid & 63, part = tid >> 6;
            const float4* Wv = (const float4*)d_Wrs;
            float4 acc = make_float4(0.f, 0.f, 0.f, 0.f);
            const int b0 = part * 64;
#pragma unroll 8
            for (int bb = b0; bb < b0 + 64; bb++)
                fma4(acc, vv_s[bb], __ldg(&Wv[bb * 64 + cg]));
            ((float4*)red_s)[part * 64 + cg] = acc;
        } else if (has_tt) {
            const int t2 = tid - Hd, cg = t2 & 63, part = t2 >> 6;
            const float4* Wv = (const float4*)d_TTW;
            float4 acc = make_float4(0.f, 0.f, 0.f, 0.f);
            const int b0 = part * 128;
            if (part < 2) {
#pragma unroll 8
                for (int bb = b0; bb < b0 + 128; bb++)
                    fma4(acc, vv_s[bb], __ldg(&Wv[bb * 64 + cg]));
            } else {
#pragma unroll 8
                for (int bb = b0; bb < b0 + 128; bb++)
                    fma4(acc, m_s[bb - Hd], __ldg(&Wv[bb * 64 + cg]));
            }
            ((float4*)red_s)[256 + part * 64 + cg] = acc;
        }
        __syncthreads();

        // ---- reduce + write ns / TT ----
        if (tid < Hd) {
            float ns = __ldg(&br[tid]) + red_s[tid] + red_s[256 + tid]
                     + red_s[512 + tid] + red_s[768 + tid];
            __stcg(&d_states[(n * HISTN + wslot) * Hd + tid], ns);
            if (has_nm) cat_s[tid] = ns;
        } else if (has_tt) {
            const int t2 = tid - Hd;
            float tt = __ldg(&d_bTT[t2]) + red_s[1024 + t2] + red_s[1280 + t2]
                     + red_s[1536 + t2] + red_s[1792 + t2];
            __stcg(&d_TTm[i * Hd + t2], tt);
            if (has_nm) cat_s[Hd + t2] = m_s[t2];
        }
        __threadfence();
        __syncthreads();
        // publish: state ready; TT ready (level 1)
        if (tid == 0) flagS[i] = 1;
        else if (tid == 32 && has_tt && !has_nm) flagT[i] = 1;
        else if (tid == 64 && has_nm) flagT[i] = 1;   // NM still pending -> level 1 only

        // ---- raw message (only 71 steps): NM = [ns;m] @ Wm + bm ----
        if (has_nm) {
            const int cg = tid & 63, part = tid >> 6;   // 8 parts x 64 K each
            const float4* Wv = (const float4*)Wm;
            float4 acc = make_float4(0.f, 0.f, 0.f, 0.f);
            const int b0 = part * 64;
#pragma unroll 8
            for (int bb = b0; bb < b0 + 64; bb++)
                fma4(acc, cat_s[bb], __ldg(&Wv[bb * 64 + cg]));
            ((float4*)red_s)[part * 64 + cg] = acc;
            __syncthreads();
            if (tid < Hd) {
                float nm = __ldg(&bm[tid]);
#pragma unroll
                for (int p = 0; p < 8; p++) nm += red_s[p * 256 + tid];
                __stcg(&d_NM[i * Md + tid], nm);
            }
            __threadfence();
            __syncthreads();
            if (tid == 0) flagT[i] = 2;
        }
    }

    // ---- all steps done -> one barrier -> fused output head ----
    gen = grid_barrier(gen);

    {   // warp per (p,n) tile: out[p,n,:] = log_softmax(final_n @ Wd[p] + bd[p])
        const int w = tid >> 5, lane = tid & 31;
        const int t2 = blockIdx.x * 16 + w;
        if (t2 < Pd * Ns) {
            const int p = t2 >> 9, n = t2 & (Ns - 1);
            const int fs = d_fslot[n];
            const float* sp = &d_states[(n * HISTN + fs) * Hd];
            float acc0 = __ldg(&bd[p * Od + lane]);
            float acc1 = __ldg(&bd[p * Od + lane + 32]);
#pragma unroll 4
            for (int h = 0; h < Hd; h++) {
                float f = __ldcg(&sp[h]);
                acc0 += f * __ldg(&Wd[(p * Hd + h) * Od + lane]);
                acc1 += f * __ldg(&Wd[(p * Hd + h) * Od + lane + 32]);
            }
            float mx = fmaxf(acc0, acc1);
#pragma unroll
            for (int o = 16; o; o >>= 1) mx = fmaxf(mx, __shfl_xor_sync(0xffffffffu, mx, o));
            float sum = expf(acc0 - mx) + expf(acc1 - mx);
#pragma unroll
            for (int o = 16; o; o >>= 1) sum += __shfl_xor_sync(0xffffffffu, sum, o);
            float lse = mx + logf(sum);
            out[(p * Ns + n) * Od + lane]      = acc0 - lse;
            out[(p * Ns + n) * Od + lane + 32] = acc1 - lse;
        }
    }
}

// ---------------- launch -----------------------------------------------------
extern "C" void kernel_launch(void* const* d_in, const int* in_sizes, int n_in,
                              void* d_out, int out_size) {
    const float* xa   = (const float*)d_in[0];
    const int*   nbrs = (const int*)  d_in[1];
    const float* fm   = (const float*)d_in[2];
    const float* We   = (const float*)d_in[3];
    const float* be   = (const float*)d_in[4];
    const float* Wq   = (const float*)d_in[5];
    const float* bq   = (const float*)d_in[6];
    const float* Wk   = (const float*)d_in[7];
    // d_in[8] = bk: cancels in softmax (constant logit shift) — unused
    const float* Wr   = (const float*)d_in[9];
    const float* br   = (const float*)d_in[10];
    const float* Wm   = (const float*)d_in[11];
    const float* bm   = (const float*)d_in[12];
    const float* Wd   = (const float*)d_in[13];
    const float* bd   = (const float*)d_in[14];
    float* out = (float*)d_out;

    // dynamic smem for the builder: q,prevs,lvl,nb,scr,cnt
    const int BUILD_SMEM = (3 * STEPS + Ns * DEG + Ns * CAPS + Ns) * (int)sizeof(int);
    cudaFuncSetAttribute(k_build, cudaFuncAttributeMaxDynamicSharedMemorySize, BUILD_SMEM);

    k_build<<<1, 1024, BUILD_SMEM>>>(nbrs);                 // #1
    k_prep1<<<853, 256>>>(Wk, Wr, xa, We, be, br, Wm, bm);  // #2 (+flag reset)
    k_prep2<<<73, 256>>>(Wq, bq, Wk, Wm, fm);               // #3
    k_main<<<GRIDB, 512>>>(fm, br, Wm, bm, Wd, bd, out);    // #4  <- ncu target
}